// round 11
// baseline (speedup 1.0000x reference)
#include <cuda_runtime.h>
#include <cuda_bf16.h>
#include <math.h>
#include <stdint.h>

#define BB 16
#define LL 512
#define CC 1024
#define NH 8
#define HD 128
#define MM (BB*LL)        // 8192 rows
#define N3 (3*CC)         // 3072
#define HM ((size_t)BB*NH*LL*HD)   // head-major elements

// Scratch (static device globals — no runtime allocation)
__device__ __nv_bfloat16 g_a_hi[(size_t)MM*CC];
__device__ __nv_bfloat16 g_a_lo[(size_t)MM*CC];
__device__ __nv_bfloat16 g_w_hi[(size_t)N3*CC];
__device__ __nv_bfloat16 g_w_lo[(size_t)N3*CC];
// head-major [bh][l][d] outputs of the projection
__device__ __nv_bfloat16 g_q_hi[HM];   // sig(qk) hi
__device__ __nv_bfloat16 g_q_lo[HM];
__device__ __nv_bfloat16 g_v_hi[HM];
__device__ __nv_bfloat16 g_v_lo[HM];
__device__ float g_res[HM];

__device__ __forceinline__ float sigmoidf(float v) {
    return 1.0f / (1.0f + expf(-v));
}

// ---------------- mma / async helpers (plain sm_80+ features) ----------------
__device__ __forceinline__ uint32_t smem_u32(const void* p) {
    return (uint32_t)__cvta_generic_to_shared((void*)p);
}
__device__ __forceinline__ void cp16(uint32_t dst, const void* src) {
    asm volatile("cp.async.cg.shared.global [%0], [%1], 16;" :: "r"(dst), "l"(src));
}
__device__ __forceinline__ void cp_commit() {
    asm volatile("cp.async.commit_group;" ::: "memory");
}
template<int N> __device__ __forceinline__ void cp_wait() {
    asm volatile("cp.async.wait_group %0;" :: "n"(N) : "memory");
}
__device__ __forceinline__ void ldm4(uint32_t* r, uint32_t addr) {
    asm volatile("ldmatrix.sync.aligned.m8n8.x4.shared.b16 {%0,%1,%2,%3},[%4];"
        : "=r"(r[0]), "=r"(r[1]), "=r"(r[2]), "=r"(r[3]) : "r"(addr));
}
__device__ __forceinline__ void ldm4t(uint32_t* r, uint32_t addr) {
    asm volatile("ldmatrix.sync.aligned.m8n8.x4.trans.shared.b16 {%0,%1,%2,%3},[%4];"
        : "=r"(r[0]), "=r"(r[1]), "=r"(r[2]), "=r"(r[3]) : "r"(addr));
}
__device__ __forceinline__ void mma16816(float* d, const uint32_t* a, const uint32_t* b) {
    asm volatile("mma.sync.aligned.m16n8k16.row.col.f32.bf16.bf16.f32 "
        "{%0,%1,%2,%3},{%4,%5,%6,%7},{%8,%9},{%0,%1,%2,%3};"
        : "+f"(d[0]), "+f"(d[1]), "+f"(d[2]), "+f"(d[3])
        : "r"(a[0]), "r"(a[1]), "r"(a[2]), "r"(a[3]), "r"(b[0]), "r"(b[1]));
}
__device__ __forceinline__ uint32_t bpack(__nv_bfloat16 a, __nv_bfloat16 b) {
    __nv_bfloat162 t = __halves2bfloat162(a, b);
    return *(uint32_t*)&t;
}
__device__ __forceinline__ void bsplit(float v, __nv_bfloat16& h, __nv_bfloat16& l) {
    h = __float2bfloat16(v);
    l = __float2bfloat16(v - __bfloat162float(h));
}

// ---------------------------------------------------------------------------
// K1: fused degree + gate. Warp per row.
// ---------------------------------------------------------------------------
__global__ __launch_bounds__(256) void dgate_kernel(const float* __restrict__ adj,
                                                    const float* __restrict__ x,
                                                    const float* __restrict__ Wd,
                                                    const float* __restrict__ bd) {
    int row = (blockIdx.x * blockDim.x + threadIdx.x) >> 5;
    int lane = threadIdx.x & 31;
    if (row >= MM) return;
    const float4* arow = (const float4*)(adj + (size_t)row * LL);
    float s = 0.0f;
    #pragma unroll
    for (int j = 0; j < 4; j++) {
        float4 v = arow[lane + 32*j];
        s += v.x + v.y + v.z + v.w;
    }
    #pragma unroll
    for (int o = 16; o > 0; o >>= 1) s += __shfl_xor_sync(0xffffffffu, s, o);
    float deg = s;

    const float4* xr = (const float4*)(x + (size_t)row * CC);
    #pragma unroll
    for (int j = 0; j < 8; j++) {
        int c4 = lane + 32*j;
        float4 xv = xr[c4];
        float4 wv = ((const float4*)Wd)[c4];
        float4 bv = ((const float4*)bd)[c4];
        float v[4];
        v[0] = xv.x * sigmoidf(deg*wv.x + bv.x);
        v[1] = xv.y * sigmoidf(deg*wv.y + bv.y);
        v[2] = xv.z * sigmoidf(deg*wv.z + bv.z);
        v[3] = xv.w * sigmoidf(deg*wv.w + bv.w);
        __nv_bfloat16 h[4], l[4];
        #pragma unroll
        for (int u = 0; u < 4; u++) bsplit(v[u], h[u], l[u]);
        size_t idx = (size_t)row * CC + c4 * 4;
        *(uint2*)&g_a_hi[idx] = *(uint2*)h;
        *(uint2*)&g_a_lo[idx] = *(uint2*)l;
    }
}

// ---------------------------------------------------------------------------
// K2b: W[1024,3072] -> W^T[3072,1024] bf16 hi/lo
// ---------------------------------------------------------------------------
__global__ void wprep_kernel(const float* __restrict__ W) {
    __shared__ float t[32][33];
    int n0 = blockIdx.x * 32;
    int k0 = blockIdx.y * 32;
    int tx = threadIdx.x, ty = threadIdx.y;   // (32, 8)
    #pragma unroll
    for (int i = ty; i < 32; i += 8)
        t[i][tx] = W[(size_t)(k0 + i) * N3 + n0 + tx];
    __syncthreads();
    #pragma unroll
    for (int i = ty; i < 32; i += 8) {
        float v = t[tx][i];
        __nv_bfloat16 h, l;
        bsplit(v, h, l);
        size_t idx = (size_t)(n0 + i) * CC + k0 + tx;
        g_w_hi[idx] = h;
        g_w_lo[idx] = l;
    }
}

// ---------------------------------------------------------------------------
// K3: HMMA bf16-split GEMM, 256x128 tile, k32 chunks, 2-stage cp.async.
// Halves B re-reads (L2 feed was the binder at 128x128) and doubles
// compute-per-barrier. Per warp per k16: 16 ldmatrix + 96 MMA (6:1).
// ---------------------------------------------------------------------------
#define ROWB 80                       // bytes per smem row (32 bf16 + pad)
#define ATILE (256*ROWB)              // 20480 B
#define BTILE (128*ROWB)              // 10240 B
#define STAGE (2*ATILE + 2*BTILE)     // Ah|Al|Bh|Bl = 61440 B
#define SG_SMEM (2*STAGE)             // 122880 B -> 1 CTA/SM

__global__ __launch_bounds__(256, 1) void sgemm_mma(const float* __restrict__ bias) {
    extern __shared__ char sm[];
    uint32_t smb = smem_u32(sm);
    int tid = threadIdx.x, wid = tid >> 5, lane = tid & 31;
    int bx = blockIdx.x, by = blockIdx.y;
    int wm = wid & 3;        // 4 warps over M: 64 rows each
    int wn = wid >> 2;       // 2 warps over N: 64 cols each

    const __nv_bfloat16* Ah = g_a_hi + (size_t)by * 256 * CC;
    const __nv_bfloat16* Al = g_a_lo + (size_t)by * 256 * CC;
    const __nv_bfloat16* Bh = g_w_hi + (size_t)bx * 128 * CC;
    const __nv_bfloat16* Bl = g_w_lo + (size_t)bx * 128 * CC;

    float acc[4][8][4];
    #pragma unroll
    for (int t = 0; t < 4; t++)
        #pragma unroll
        for (int j = 0; j < 8; j++)
            #pragma unroll
            for (int u = 0; u < 4; u++) acc[t][j][u] = 0.0f;

    auto load_chunk = [&](int stage, int k0) {
        uint32_t base = smb + stage * STAGE;
        #pragma unroll
        for (int q = 0; q < 4; q++) {          // A: 256 rows x 4 segs
            int c = tid + 256 * q;
            int row = c >> 2, s = c & 3;
            uint32_t off = (uint32_t)(row * ROWB + s * 16);
            size_t go = (size_t)row * CC + k0 + s * 8;
            cp16(base + off,         Ah + go);
            cp16(base + ATILE + off, Al + go);
        }
        #pragma unroll
        for (int q = 0; q < 2; q++) {          // B: 128 rows x 4 segs
            int c = tid + 256 * q;
            int row = c >> 2, s = c & 3;
            uint32_t off = (uint32_t)(row * ROWB + s * 16);
            size_t go = (size_t)row * CC + k0 + s * 8;
            cp16(base + 2*ATILE + off,         Bh + go);
            cp16(base + 2*ATILE + BTILE + off, Bl + go);
        }
        cp_commit();
    };

    int li = lane >> 3, lr = lane & 7;
    int a_rowbase = wm * 64 + (li & 1) * 8 + lr;
    int a_seg = li >> 1;
    int b_rowbase = wn * 64 + (li >> 1) * 8 + lr;
    int b_seg = li & 1;

    load_chunk(0, 0);

    #pragma unroll 1
    for (int i = 0; i < 32; i++) {
        cp_wait<0>();
        __syncthreads();
        if (i < 31) load_chunk((i + 1) & 1, (i + 1) * 32);

        uint32_t sb = smb + (i & 1) * STAGE;
        #pragma unroll
        for (int ks = 0; ks < 2; ks++) {
            uint32_t ah[4][4], al[4][4];
            #pragma unroll
            for (int t = 0; t < 4; t++) {
                uint32_t aoff = (uint32_t)((a_rowbase + t*16) * ROWB + (ks*2 + a_seg) * 16);
                ldm4(ah[t], sb + aoff);
                ldm4(al[t], sb + ATILE + aoff);
            }
            uint32_t bh[4][4], bl[4][4];
            #pragma unroll
            for (int bt = 0; bt < 4; bt++) {
                uint32_t boff = (uint32_t)((b_rowbase + bt*16) * ROWB + (ks*2 + b_seg) * 16);
                ldm4(bh[bt], sb + 2*ATILE + boff);
                ldm4(bl[bt], sb + 2*ATILE + BTILE + boff);
            }
            #pragma unroll
            for (int t = 0; t < 4; t++) {
                #pragma unroll
                for (int j = 0; j < 8; j++) {
                    const uint32_t* bhp = &bh[j >> 1][(j & 1) * 2];
                    const uint32_t* blp = &bl[j >> 1][(j & 1) * 2];
                    mma16816(acc[t][j], ah[t], bhp);
                    mma16816(acc[t][j], ah[t], blp);
                    mma16816(acc[t][j], al[t], bhp);
                }
            }
        }
    }

    // epilogue -> head-major arrays
    int third = bx >> 3;          // 0=qk, 1=res, 2=value
    int head = bx & 7;
    #pragma unroll
    for (int t = 0; t < 4; t++) {
        int gr0 = by * 256 + wm * 64 + t * 16 + (lane >> 2);
        #pragma unroll
        for (int j = 0; j < 8; j++) {
            int col = wn * 64 + j * 8 + (lane & 3) * 2;
            float bx0 = bias[bx * 128 + col];
            float bx1 = bias[bx * 128 + col + 1];
            #pragma unroll
            for (int rsel = 0; rsel < 2; rsel++) {
                int gr = gr0 + rsel * 8;
                float v0 = acc[t][j][rsel*2 + 0] + bx0;
                float v1 = acc[t][j][rsel*2 + 1] + bx1;
                int b = gr >> 9, l = gr & 511;
                size_t idx = ((size_t)((b << 3) + head) * LL + l) * HD + col;
                if (third == 0) {
                    v0 = sigmoidf(v0); v1 = sigmoidf(v1);
                    __nv_bfloat16 h0,l0,h1,l1;
                    bsplit(v0,h0,l0); bsplit(v1,h1,l1);
                    *(uint32_t*)&g_q_hi[idx] = bpack(h0,h1);
                    *(uint32_t*)&g_q_lo[idx] = bpack(l0,l1);
                } else if (third == 1) {
                    *(float2*)&g_res[idx] = make_float2(v0, v1);
                } else {
                    __nv_bfloat16 h0,l0,h1,l1;
                    bsplit(v0,h0,l0); bsplit(v1,h1,l1);
                    *(uint32_t*)&g_v_hi[idx] = bpack(h0,h1);
                    *(uint32_t*)&g_v_lo[idx] = bpack(l0,l1);
                }
            }
        }
    }
}

// ---------------------------------------------------------------------------
// K4: HMMA attention, Q fragments hoisted to registers (round-10 version).
// ---------------------------------------------------------------------------
#define QROWB 272
#define KROWB 272
#define ADJROWB 144
#define QTILE (128*QROWB)
#define KTILE (32*KROWB)
#define STAGEA (4*KTILE + 128*ADJROWB)
#define AT_SMEM (2*QTILE + 2*STAGEA)

__global__ __launch_bounds__(256, 1) void attn3_kernel(const float* __restrict__ adj,
                                                       float* __restrict__ out) {
    extern __shared__ char sm[];
    uint32_t smb = smem_u32(sm);
    int tid = threadIdx.x, warp = tid >> 5, lane = tid & 31;
    int li = lane >> 3, lr = lane & 7;
    int rt = blockIdx.x, bh = blockIdx.y;
    int b = bh >> 3, h = bh & 7;
    int r0 = rt * 128;
    int wr = warp * 16;

    const uint32_t QH = smb, QL = smb + QTILE;
    const float scale = 0.08838834764831845f;

    #pragma unroll
    for (int i = 0; i < 16; i++) {
        int idx = tid + 256 * i;
        int arr = idx >> 11, rem = idx & 2047;
        int row = rem >> 4, seg = rem & 15;
        const __nv_bfloat16* src = arr ? g_q_lo : g_q_hi;
        cp16(QH + arr*QTILE + (uint32_t)(row*QROWB + seg*16),
             src + ((size_t)bh*LL + r0 + row)*HD + seg*8);
    }
    cp_commit();

    auto load_stage = [&](int s, int c0) {
        uint32_t SB = smb + 2*QTILE + s*STAGEA;
        #pragma unroll
        for (int i = 0; i < 12; i++) {
            int idx = tid + 256 * i;
            if (idx < 2048) {
                int which = idx >> 10;
                int arr = (idx >> 9) & 1;
                int rem = idx & 511;
                int row = rem >> 4, seg = rem & 15;
                const __nv_bfloat16* src =
                    which ? (arr ? g_v_lo : g_v_hi) : (arr ? g_q_lo : g_q_hi);
                cp16(SB + which*2*KTILE + arr*KTILE + (uint32_t)(row*KROWB + seg*16),
                     src + ((size_t)bh*LL + c0 + row)*HD + seg*8);
            } else {
                int rem = idx - 2048;
                int row = rem >> 3, g = rem & 7;
                cp16(SB + 4*KTILE + (uint32_t)(row*ADJROWB + g*16),
                     adj + ((size_t)(b*LL + r0 + row))*LL + c0 + g*4);
            }
        }
        cp_commit();
    };

    load_stage(0, 0);
    cp_wait<0>();
    __syncthreads();

    // hoist Q fragments: invariant across all key chunks
    uint32_t qh[8][4], ql[8][4];
    #pragma unroll
    for (int ks = 0; ks < 8; ks++) {
        uint32_t aoff = (uint32_t)((wr + (li&1)*8 + lr)*QROWB + ks*32 + (li>>1)*16);
        ldm4(qh[ks], QH + aoff);
        ldm4(ql[ks], QL + aoff);
    }

    float Oacc[16][4];
    #pragma unroll
    for (int n = 0; n < 16; n++)
        #pragma unroll
        for (int u = 0; u < 4; u++) Oacc[n][u] = 0.0f;
    float d0 = 0.0f, d1 = 0.0f;

    #pragma unroll 1
    for (int c = 0; c < 16; c++) {
        if (c < 15) load_stage((c + 1) & 1, (c + 1) * 32);

        uint32_t SB = smb + 2*QTILE + (c & 1)*STAGEA;
        uint32_t KHB = SB, KLB = SB + KTILE, VHB = SB + 2*KTILE, VLB = SB + 3*KTILE;
        const float* adjs = (const float*)(sm + 2*QTILE + (c & 1)*STAGEA + 4*KTILE);

        float S[4][4];
        #pragma unroll
        for (int j = 0; j < 4; j++)
            #pragma unroll
            for (int u = 0; u < 4; u++) S[j][u] = 0.0f;

        #pragma unroll
        for (int ks = 0; ks < 8; ks++) {
            uint32_t kh[2][4], kl[2][4];
            #pragma unroll
            for (int g = 0; g < 2; g++) {
                uint32_t boff = (uint32_t)((g*16 + (li>>1)*8 + lr)*KROWB + ks*32 + (li&1)*16);
                ldm4(kh[g], KHB + boff);
                ldm4(kl[g], KLB + boff);
            }
            #pragma unroll
            for (int j = 0; j < 4; j++) {
                const uint32_t* ph = &kh[j>>1][(j&1)*2];
                const uint32_t* pl = &kl[j>>1][(j&1)*2];
                mma16816(S[j], qh[ks], ph);
                mma16816(S[j], qh[ks], pl);
                mma16816(S[j], ql[ks], ph);
            }
        }

        uint32_t Th[4][2], Tl[4][2];
        int ra = wr + (lane >> 2);
        #pragma unroll
        for (int j = 0; j < 4; j++) {
            int cb = j*8 + (lane & 3)*2;
            float a00 = adjs[ra*36 + cb],     a01 = adjs[ra*36 + cb + 1];
            float a10 = adjs[(ra+8)*36 + cb], a11 = adjs[(ra+8)*36 + cb + 1];
            float T00 = (a00 != 0.0f) ? S[j][0]*scale : 0.0f;
            float T01 = (a01 != 0.0f) ? S[j][1]*scale : 0.0f;
            float T10 = (a10 != 0.0f) ? S[j][2]*scale : 0.0f;
            float T11 = (a11 != 0.0f) ? S[j][3]*scale : 0.0f;
            d0 += T00 + T01;
            d1 += T10 + T11;
            __nv_bfloat16 h0,l0,h1,l1;
            bsplit(T00,h0,l0); bsplit(T01,h1,l1);
            Th[j][0] = bpack(h0,h1); Tl[j][0] = bpack(l0,l1);
            bsplit(T10,h0,l0); bsplit(T11,h1,l1);
            Th[j][1] = bpack(h0,h1); Tl[j][1] = bpack(l0,l1);
        }

        #pragma unroll
        for (int kk = 0; kk < 2; kk++) {
            uint32_t ahf[4] = {Th[2*kk][0], Th[2*kk][1], Th[2*kk+1][0], Th[2*kk+1][1]};
            uint32_t alf[4] = {Tl[2*kk][0], Tl[2*kk][1], Tl[2*kk+1][0], Tl[2*kk+1][1]};
            #pragma unroll
            for (int g = 0; g < 8; g++) {
                uint32_t bh4[4], bl4[4];
                uint32_t voff = (uint32_t)((kk*16 + (li&1)*8 + lr)*KROWB + g*32 + (li>>1)*16);
                ldm4t(bh4, VHB + voff);
                ldm4t(bl4, VLB + voff);
                #pragma unroll
                for (int j = 0; j < 2; j++) {
                    int nt = g*2 + j;
                    const uint32_t* pb = &bh4[j*2];
                    const uint32_t* pl = &bl4[j*2];
                    mma16816(Oacc[nt], ahf, pb);
                    mma16816(Oacc[nt], ahf, pl);
                    mma16816(Oacc[nt], alf, pb);
                }
            }
        }

        if (c < 15) cp_wait<0>();
        __syncthreads();
    }

    d0 += __shfl_xor_sync(0xffffffffu, d0, 1);
    d0 += __shfl_xor_sync(0xffffffffu, d0, 2);
    d1 += __shfl_xor_sync(0xffffffffu, d1, 1);
    d1 += __shfl_xor_sync(0xffffffffu, d1, 2);
    float inv0 = 1.0f / (d0 + 1e-6f);
    float inv1 = 1.0f / (d1 + 1e-6f);

    int gr0 = r0 + wr + (lane >> 2);
    #pragma unroll
    for (int nt = 0; nt < 16; nt++) {
        int col = nt*8 + (lane & 3)*2;
        size_t i0 = ((size_t)bh*LL + gr0)*HD + col;
        float2 rs0 = *(const float2*)(g_res + i0);
        float2 rs1 = *(const float2*)(g_res + i0 + 8*HD);
        float* o0 = out + ((size_t)(b*LL + gr0))*CC + h*HD + col;
        *(float2*)o0 = make_float2(
            fmaxf(Oacc[nt][0]*inv0 + rs0.x, 0.0f),
            fmaxf(Oacc[nt][1]*inv0 + rs0.y, 0.0f));
        *(float2*)(o0 + 8*CC) = make_float2(
            fmaxf(Oacc[nt][2]*inv1 + rs1.x, 0.0f),
            fmaxf(Oacc[nt][3]*inv1 + rs1.y, 0.0f));
    }
}

// ---------------------------------------------------------------------------
extern "C" void kernel_launch(void* const* d_in, const int* in_sizes, int n_in,
                              void* d_out, int out_size) {
    const float* x    = (const float*)d_in[0];
    const float* adj  = (const float*)d_in[1];
    const float* Wqkv = (const float*)d_in[2];
    const float* bqkv = (const float*)d_in[3];
    const float* Wd   = (const float*)d_in[4];
    const float* bd   = (const float*)d_in[5];
    float* out = (float*)d_out;

    cudaFuncSetAttribute(sgemm_mma,
                         cudaFuncAttributeMaxDynamicSharedMemorySize, SG_SMEM);
    cudaFuncSetAttribute(attn3_kernel,
                         cudaFuncAttributeMaxDynamicSharedMemorySize, AT_SMEM);

    dgate_kernel<<<MM/8, 256>>>(adj, x, Wd, bd);
    wprep_kernel<<<dim3(N3/32, CC/32), dim3(32, 8)>>>(Wqkv);
    sgemm_mma<<<dim3(N3/128, MM/256), 256, SG_SMEM>>>(bqkv);
    attn3_kernel<<<dim3(LL/128, NH*BB), 256, AT_SMEM>>>(adj, out);
}

// round 14
// speedup vs baseline: 1.1197x; 1.1197x over previous
#include <cuda_runtime.h>
#include <cuda_bf16.h>
#include <math.h>
#include <stdint.h>

#define BB 16
#define LL 512
#define CC 1024
#define NH 8
#define HD 128
#define MM (BB*LL)        // 8192 rows
#define N3 (3*CC)         // 3072
#define HM ((size_t)BB*NH*LL*HD)   // head-major elements

// Scratch (static device globals — no runtime allocation)
__device__ __nv_bfloat16 g_a_hi[(size_t)MM*CC];
__device__ __nv_bfloat16 g_a_lo[(size_t)MM*CC];
__device__ __nv_bfloat16 g_w_hi[(size_t)N3*CC];
__device__ __nv_bfloat16 g_w_lo[(size_t)N3*CC];
// head-major [bh][l][d] outputs of the projection
__device__ __nv_bfloat16 g_q_hi[HM];   // sig(qk) hi
__device__ __nv_bfloat16 g_q_lo[HM];
__device__ __nv_bfloat16 g_v_hi[HM];
__device__ __nv_bfloat16 g_v_lo[HM];
__device__ float g_res[HM];

__device__ __forceinline__ float sigmoidf(float v) {
    return 1.0f / (1.0f + expf(-v));
}

// ---------------- mma / async helpers (plain sm_80+ features) ----------------
__device__ __forceinline__ uint32_t smem_u32(const void* p) {
    return (uint32_t)__cvta_generic_to_shared((void*)p);
}
__device__ __forceinline__ void cp16(uint32_t dst, const void* src) {
    asm volatile("cp.async.cg.shared.global [%0], [%1], 16;" :: "r"(dst), "l"(src));
}
__device__ __forceinline__ void cp_commit() {
    asm volatile("cp.async.commit_group;" ::: "memory");
}
template<int N> __device__ __forceinline__ void cp_wait() {
    asm volatile("cp.async.wait_group %0;" :: "n"(N) : "memory");
}
__device__ __forceinline__ void ldm4(uint32_t* r, uint32_t addr) {
    asm volatile("ldmatrix.sync.aligned.m8n8.x4.shared.b16 {%0,%1,%2,%3},[%4];"
        : "=r"(r[0]), "=r"(r[1]), "=r"(r[2]), "=r"(r[3]) : "r"(addr));
}
__device__ __forceinline__ void ldm4t(uint32_t* r, uint32_t addr) {
    asm volatile("ldmatrix.sync.aligned.m8n8.x4.trans.shared.b16 {%0,%1,%2,%3},[%4];"
        : "=r"(r[0]), "=r"(r[1]), "=r"(r[2]), "=r"(r[3]) : "r"(addr));
}
__device__ __forceinline__ void mma16816(float* d, const uint32_t* a, const uint32_t* b) {
    asm volatile("mma.sync.aligned.m16n8k16.row.col.f32.bf16.bf16.f32 "
        "{%0,%1,%2,%3},{%4,%5,%6,%7},{%8,%9},{%0,%1,%2,%3};"
        : "+f"(d[0]), "+f"(d[1]), "+f"(d[2]), "+f"(d[3])
        : "r"(a[0]), "r"(a[1]), "r"(a[2]), "r"(a[3]), "r"(b[0]), "r"(b[1]));
}
__device__ __forceinline__ uint32_t bpack(__nv_bfloat16 a, __nv_bfloat16 b) {
    __nv_bfloat162 t = __halves2bfloat162(a, b);
    return *(uint32_t*)&t;
}
__device__ __forceinline__ void bsplit(float v, __nv_bfloat16& h, __nv_bfloat16& l) {
    h = __float2bfloat16(v);
    l = __float2bfloat16(v - __bfloat162float(h));
}

// ---------------------------------------------------------------------------
// K1: fused prep. Blocks [0,1024): degree+gate (warp per row).
//     Blocks [1024,4096): W transpose + bf16 hi/lo split (32x32 tiles).
// ---------------------------------------------------------------------------
#define DGATE_BLOCKS (MM/8)          // 1024
#define WPREP_BLOCKS ((N3/32)*(CC/32))   // 96*32 = 3072

__global__ __launch_bounds__(256) void prep_kernel(const float* __restrict__ adj,
                                                   const float* __restrict__ x,
                                                   const float* __restrict__ Wd,
                                                   const float* __restrict__ bd,
                                                   const float* __restrict__ W) {
    __shared__ float t[32][33];
    int tid = threadIdx.x;

    if (blockIdx.x < DGATE_BLOCKS) {
        // ---- degree + gate ----
        int row = (blockIdx.x * 256 + tid) >> 5;
        int lane = tid & 31;
        const float4* arow = (const float4*)(adj + (size_t)row * LL);
        float s = 0.0f;
        #pragma unroll
        for (int j = 0; j < 4; j++) {
            float4 v = arow[lane + 32*j];
            s += v.x + v.y + v.z + v.w;
        }
        #pragma unroll
        for (int o = 16; o > 0; o >>= 1) s += __shfl_xor_sync(0xffffffffu, s, o);
        float deg = s;

        const float4* xr = (const float4*)(x + (size_t)row * CC);
        #pragma unroll
        for (int j = 0; j < 8; j++) {
            int c4 = lane + 32*j;
            float4 xv = xr[c4];
            float4 wv = ((const float4*)Wd)[c4];
            float4 bv = ((const float4*)bd)[c4];
            float v[4];
            v[0] = xv.x * sigmoidf(deg*wv.x + bv.x);
            v[1] = xv.y * sigmoidf(deg*wv.y + bv.y);
            v[2] = xv.z * sigmoidf(deg*wv.z + bv.z);
            v[3] = xv.w * sigmoidf(deg*wv.w + bv.w);
            __nv_bfloat16 h[4], l[4];
            #pragma unroll
            for (int u = 0; u < 4; u++) bsplit(v[u], h[u], l[u]);
            size_t idx = (size_t)row * CC + c4 * 4;
            *(uint2*)&g_a_hi[idx] = *(uint2*)h;
            *(uint2*)&g_a_lo[idx] = *(uint2*)l;
        }
    } else {
        // ---- W transpose + split ----
        int bid = blockIdx.x - DGATE_BLOCKS;
        int n0 = (bid % (N3/32)) * 32;
        int k0 = (bid / (N3/32)) * 32;
        int tx = tid & 31, ty = tid >> 5;     // (32, 8)
        #pragma unroll
        for (int i = ty; i < 32; i += 8)
            t[i][tx] = W[(size_t)(k0 + i) * N3 + n0 + tx];
        __syncthreads();
        #pragma unroll
        for (int i = ty; i < 32; i += 8) {
            float v = t[tx][i];
            __nv_bfloat16 h, l;
            bsplit(v, h, l);
            size_t idx = (size_t)(n0 + i) * CC + k0 + tx;
            g_w_hi[idx] = h;
            g_w_lo[idx] = l;
        }
    }
}

// ---------------------------------------------------------------------------
// K3: HMMA bf16-split GEMM (R5 optimum: k32, 2-stage, ROWB=80, 2 CTA/SM)
// ---------------------------------------------------------------------------
#define ROWB 80                      // bytes per smem row (32 bf16 + pad)
#define TILE (128*ROWB)              // 10240 B
#define STAGE (4*TILE)               // Ah|Al|Bh|Bl = 40960 B
#define SG_SMEM (2*STAGE)            // 80 KB -> 2 CTA/SM

__global__ __launch_bounds__(256) void sgemm_mma(const float* __restrict__ bias) {
    extern __shared__ char sm[];
    uint32_t smb = smem_u32(sm);
    int tid = threadIdx.x, wid = tid >> 5, lane = tid & 31;
    int bx = blockIdx.x, by = blockIdx.y;
    int wm = wid & 3;
    int wn = wid >> 2;

    const __nv_bfloat16* Ah = g_a_hi + (size_t)by * 128 * CC;
    const __nv_bfloat16* Al = g_a_lo + (size_t)by * 128 * CC;
    const __nv_bfloat16* Bh = g_w_hi + (size_t)bx * 128 * CC;
    const __nv_bfloat16* Bl = g_w_lo + (size_t)bx * 128 * CC;

    float acc[2][8][4];
    #pragma unroll
    for (int t = 0; t < 2; t++)
        #pragma unroll
        for (int j = 0; j < 8; j++)
            #pragma unroll
            for (int u = 0; u < 4; u++) acc[t][j][u] = 0.0f;

    auto load_chunk = [&](int stage, int k0) {
        uint32_t base = smb + stage * STAGE;
        #pragma unroll
        for (int q = 0; q < 2; q++) {
            int c = tid + 256 * q;
            int row = c >> 2, s = c & 3;
            uint32_t off = (uint32_t)(row * ROWB + s * 16);
            size_t go = (size_t)row * CC + k0 + s * 8;
            cp16(base + off,            Ah + go);
            cp16(base + TILE + off,     Al + go);
            cp16(base + 2*TILE + off,   Bh + go);
            cp16(base + 3*TILE + off,   Bl + go);
        }
        cp_commit();
    };

    int li = lane >> 3, lr = lane & 7;
    int a_row = wm * 32 + (li & 1) * 8 + lr;
    int a_seg = li >> 1;
    int b_rowbase = wn * 64 + (li >> 1) * 8 + lr;
    int b_seg = li & 1;

    load_chunk(0, 0);

    #pragma unroll 1
    for (int i = 0; i < 32; i++) {
        cp_wait<0>();
        __syncthreads();
        if (i < 31) load_chunk((i + 1) & 1, (i + 1) * 32);

        uint32_t sb = smb + (i & 1) * STAGE;
        #pragma unroll
        for (int ks = 0; ks < 2; ks++) {
            uint32_t ah[2][4], al[2][4];
            #pragma unroll
            for (int t = 0; t < 2; t++) {
                uint32_t aoff = (uint32_t)((a_row + t*16) * ROWB + (ks*2 + a_seg) * 16);
                ldm4(ah[t], sb + aoff);
                ldm4(al[t], sb + TILE + aoff);
            }
            #pragma unroll
            for (int half = 0; half < 2; half++) {
                uint32_t bh[2][4], bl[2][4];
                #pragma unroll
                for (int bt = 0; bt < 2; bt++) {
                    uint32_t boff = (uint32_t)((b_rowbase + half*32 + bt*16) * ROWB
                                               + (ks*2 + b_seg) * 16);
                    ldm4(bh[bt], sb + 2*TILE + boff);
                    ldm4(bl[bt], sb + 3*TILE + boff);
                }
                #pragma unroll
                for (int t = 0; t < 2; t++) {
                    #pragma unroll
                    for (int j = 0; j < 4; j++) {
                        int jj = half * 4 + j;
                        const uint32_t* bhp = &bh[j >> 1][(j & 1) * 2];
                        const uint32_t* blp = &bl[j >> 1][(j & 1) * 2];
                        mma16816(acc[t][jj], ah[t], bhp);
                        mma16816(acc[t][jj], ah[t], blp);
                        mma16816(acc[t][jj], al[t], bhp);
                    }
                }
            }
        }
    }

    // epilogue -> head-major arrays
    int third = bx >> 3;          // 0=qk, 1=res, 2=value
    int head = bx & 7;
    #pragma unroll
    for (int t = 0; t < 2; t++) {
        int gr0 = by * 128 + wm * 32 + t * 16 + (lane >> 2);
        #pragma unroll
        for (int j = 0; j < 8; j++) {
            int col = wn * 64 + j * 8 + (lane & 3) * 2;
            float bx0 = bias[bx * 128 + col];
            float bx1 = bias[bx * 128 + col + 1];
            #pragma unroll
            for (int rsel = 0; rsel < 2; rsel++) {
                int gr = gr0 + rsel * 8;
                float v0 = acc[t][j][rsel*2 + 0] + bx0;
                float v1 = acc[t][j][rsel*2 + 1] + bx1;
                int b = gr >> 9, l = gr & 511;
                size_t idx = ((size_t)((b << 3) + head) * LL + l) * HD + col;
                if (third == 0) {
                    v0 = sigmoidf(v0); v1 = sigmoidf(v1);
                    __nv_bfloat16 h0,l0,h1,l1;
                    bsplit(v0,h0,l0); bsplit(v1,h1,l1);
                    *(uint32_t*)&g_q_hi[idx] = bpack(h0,h1);
                    *(uint32_t*)&g_q_lo[idx] = bpack(l0,l1);
                } else if (third == 1) {
                    *(float2*)&g_res[idx] = make_float2(v0, v1);
                } else {
                    __nv_bfloat16 h0,l0,h1,l1;
                    bsplit(v0,h0,l0); bsplit(v1,h1,l1);
                    *(uint32_t*)&g_v_hi[idx] = bpack(h0,h1);
                    *(uint32_t*)&g_v_lo[idx] = bpack(l0,l1);
                }
            }
        }
    }
}

// ---------------------------------------------------------------------------
// K4: HMMA attention, Q fragments hoisted to registers (round-10 best).
// ---------------------------------------------------------------------------
#define QROWB 272
#define KROWB 272
#define ADJROWB 144
#define QTILE (128*QROWB)
#define KTILE (32*KROWB)
#define STAGEA (4*KTILE + 128*ADJROWB)
#define AT_SMEM (2*QTILE + 2*STAGEA)

__global__ __launch_bounds__(256, 1) void attn3_kernel(const float* __restrict__ adj,
                                                       float* __restrict__ out) {
    extern __shared__ char sm[];
    uint32_t smb = smem_u32(sm);
    int tid = threadIdx.x, warp = tid >> 5, lane = tid & 31;
    int li = lane >> 3, lr = lane & 7;
    int rt = blockIdx.x, bh = blockIdx.y;
    int b = bh >> 3, h = bh & 7;
    int r0 = rt * 128;
    int wr = warp * 16;

    const uint32_t QH = smb, QL = smb + QTILE;
    const float scale = 0.08838834764831845f;

    #pragma unroll
    for (int i = 0; i < 16; i++) {
        int idx = tid + 256 * i;
        int arr = idx >> 11, rem = idx & 2047;
        int row = rem >> 4, seg = rem & 15;
        const __nv_bfloat16* src = arr ? g_q_lo : g_q_hi;
        cp16(QH + arr*QTILE + (uint32_t)(row*QROWB + seg*16),
             src + ((size_t)bh*LL + r0 + row)*HD + seg*8);
    }
    cp_commit();

    auto load_stage = [&](int s, int c0) {
        uint32_t SB = smb + 2*QTILE + s*STAGEA;
        #pragma unroll
        for (int i = 0; i < 12; i++) {
            int idx = tid + 256 * i;
            if (idx < 2048) {
                int which = idx >> 10;
                int arr = (idx >> 9) & 1;
                int rem = idx & 511;
                int row = rem >> 4, seg = rem & 15;
                const __nv_bfloat16* src =
                    which ? (arr ? g_v_lo : g_v_hi) : (arr ? g_q_lo : g_q_hi);
                cp16(SB + which*2*KTILE + arr*KTILE + (uint32_t)(row*KROWB + seg*16),
                     src + ((size_t)bh*LL + c0 + row)*HD + seg*8);
            } else {
                int rem = idx - 2048;
                int row = rem >> 3, g = rem & 7;
                cp16(SB + 4*KTILE + (uint32_t)(row*ADJROWB + g*16),
                     adj + ((size_t)(b*LL + r0 + row))*LL + c0 + g*4);
            }
        }
        cp_commit();
    };

    load_stage(0, 0);
    cp_wait<0>();
    __syncthreads();

    // hoist Q fragments: invariant across all key chunks
    uint32_t qh[8][4], ql[8][4];
    #pragma unroll
    for (int ks = 0; ks < 8; ks++) {
        uint32_t aoff = (uint32_t)((wr + (li&1)*8 + lr)*QROWB + ks*32 + (li>>1)*16);
        ldm4(qh[ks], QH + aoff);
        ldm4(ql[ks], QL + aoff);
    }

    float Oacc[16][4];
    #pragma unroll
    for (int n = 0; n < 16; n++)
        #pragma unroll
        for (int u = 0; u < 4; u++) Oacc[n][u] = 0.0f;
    float d0 = 0.0f, d1 = 0.0f;

    #pragma unroll 1
    for (int c = 0; c < 16; c++) {
        if (c < 15) load_stage((c + 1) & 1, (c + 1) * 32);

        uint32_t SB = smb + 2*QTILE + (c & 1)*STAGEA;
        uint32_t KHB = SB, KLB = SB + KTILE, VHB = SB + 2*KTILE, VLB = SB + 3*KTILE;
        const float* adjs = (const float*)(sm + 2*QTILE + (c & 1)*STAGEA + 4*KTILE);

        float S[4][4];
        #pragma unroll
        for (int j = 0; j < 4; j++)
            #pragma unroll
            for (int u = 0; u < 4; u++) S[j][u] = 0.0f;

        #pragma unroll
        for (int ks = 0; ks < 8; ks++) {
            uint32_t kh[2][4], kl[2][4];
            #pragma unroll
            for (int g = 0; g < 2; g++) {
                uint32_t boff = (uint32_t)((g*16 + (li>>1)*8 + lr)*KROWB + ks*32 + (li&1)*16);
                ldm4(kh[g], KHB + boff);
                ldm4(kl[g], KLB + boff);
            }
            #pragma unroll
            for (int j = 0; j < 4; j++) {
                const uint32_t* ph = &kh[j>>1][(j&1)*2];
                const uint32_t* pl = &kl[j>>1][(j&1)*2];
                mma16816(S[j], qh[ks], ph);
                mma16816(S[j], qh[ks], pl);
                mma16816(S[j], ql[ks], ph);
            }
        }

        uint32_t Th[4][2], Tl[4][2];
        int ra = wr + (lane >> 2);
        #pragma unroll
        for (int j = 0; j < 4; j++) {
            int cb = j*8 + (lane & 3)*2;
            float a00 = adjs[ra*36 + cb],     a01 = adjs[ra*36 + cb + 1];
            float a10 = adjs[(ra+8)*36 + cb], a11 = adjs[(ra+8)*36 + cb + 1];
            float T00 = (a00 != 0.0f) ? S[j][0]*scale : 0.0f;
            float T01 = (a01 != 0.0f) ? S[j][1]*scale : 0.0f;
            float T10 = (a10 != 0.0f) ? S[j][2]*scale : 0.0f;
            float T11 = (a11 != 0.0f) ? S[j][3]*scale : 0.0f;
            d0 += T00 + T01;
            d1 += T10 + T11;
            __nv_bfloat16 h0,l0,h1,l1;
            bsplit(T00,h0,l0); bsplit(T01,h1,l1);
            Th[j][0] = bpack(h0,h1); Tl[j][0] = bpack(l0,l1);
            bsplit(T10,h0,l0); bsplit(T11,h1,l1);
            Th[j][1] = bpack(h0,h1); Tl[j][1] = bpack(l0,l1);
        }

        #pragma unroll
        for (int kk = 0; kk < 2; kk++) {
            uint32_t ahf[4] = {Th[2*kk][0], Th[2*kk][1], Th[2*kk+1][0], Th[2*kk+1][1]};
            uint32_t alf[4] = {Tl[2*kk][0], Tl[2*kk][1], Tl[2*kk+1][0], Tl[2*kk+1][1]};
            #pragma unroll
            for (int g = 0; g < 8; g++) {
                uint32_t bh4[4], bl4[4];
                uint32_t voff = (uint32_t)((kk*16 + (li&1)*8 + lr)*KROWB + g*32 + (li>>1)*16);
                ldm4t(bh4, VHB + voff);
                ldm4t(bl4, VLB + voff);
                #pragma unroll
                for (int j = 0; j < 2; j++) {
                    int nt = g*2 + j;
                    const uint32_t* pb = &bh4[j*2];
                    const uint32_t* pl = &bl4[j*2];
                    mma16816(Oacc[nt], ahf, pb);
                    mma16816(Oacc[nt], ahf, pl);
                    mma16816(Oacc[nt], alf, pb);
                }
            }
        }

        if (c < 15) {           // last chunk: epilogue reads only registers
            cp_wait<0>();
            __syncthreads();
        }
    }

    d0 += __shfl_xor_sync(0xffffffffu, d0, 1);
    d0 += __shfl_xor_sync(0xffffffffu, d0, 2);
    d1 += __shfl_xor_sync(0xffffffffu, d1, 1);
    d1 += __shfl_xor_sync(0xffffffffu, d1, 2);
    float inv0 = 1.0f / (d0 + 1e-6f);
    float inv1 = 1.0f / (d1 + 1e-6f);

    int gr0 = r0 + wr + (lane >> 2);
    #pragma unroll
    for (int nt = 0; nt < 16; nt++) {
        int col = nt*8 + (lane & 3)*2;
        size_t i0 = ((size_t)bh*LL + gr0)*HD + col;
        float2 rs0 = *(const float2*)(g_res + i0);
        float2 rs1 = *(const float2*)(g_res + i0 + 8*HD);
        float* o0 = out + ((size_t)(b*LL + gr0))*CC + h*HD + col;
        *(float2*)o0 = make_float2(
            fmaxf(Oacc[nt][0]*inv0 + rs0.x, 0.0f),
            fmaxf(Oacc[nt][1]*inv0 + rs0.y, 0.0f));
        *(float2*)(o0 + 8*CC) = make_float2(
            fmaxf(Oacc[nt][2]*inv1 + rs1.x, 0.0f),
            fmaxf(Oacc[nt][3]*inv1 + rs1.y, 0.0f));
    }
}

// ---------------------------------------------------------------------------
extern "C" void kernel_launch(void* const* d_in, const int* in_sizes, int n_in,
                              void* d_out, int out_size) {
    const float* x    = (const float*)d_in[0];
    const float* adj  = (const float*)d_in[1];
    const float* Wqkv = (const float*)d_in[2];
    const float* bqkv = (const float*)d_in[3];
    const float* Wd   = (const float*)d_in[4];
    const float* bd   = (const float*)d_in[5];
    float* out = (float*)d_out;

    cudaFuncSetAttribute(sgemm_mma,
                         cudaFuncAttributeMaxDynamicSharedMemorySize, SG_SMEM);
    cudaFuncSetAttribute(attn3_kernel,
                         cudaFuncAttributeMaxDynamicSharedMemorySize, AT_SMEM);

    prep_kernel<<<DGATE_BLOCKS + WPREP_BLOCKS, 256>>>(adj, x, Wd, bd, Wqkv);
    sgemm_mma<<<dim3(N3/128, MM/128), 256, SG_SMEM>>>(bqkv);
    attn3_kernel<<<dim3(LL/128, NH*BB), 256, AT_SMEM>>>(adj, out);
}

// round 15
// speedup vs baseline: 1.3705x; 1.2241x over previous
#include <cuda_runtime.h>
#include <cuda_bf16.h>
#include <math.h>
#include <stdint.h>

#define BB 16
#define LL 512
#define CC 1024
#define NH 8
#define HD 128
#define MM (BB*LL)        // 8192 rows
#define N3 (3*CC)         // 3072
#define HM ((size_t)BB*NH*LL*HD)   // head-major elements

// Scratch (static device globals — no runtime allocation)
__device__ float g_a32[(size_t)MM*CC];     // gated x, tf32-rounded (32MB)
__device__ float g_w32[(size_t)N3*CC];     // W^T, tf32-rounded (12MB)
// head-major [bh][l][d] outputs of the projection
__device__ __nv_bfloat16 g_q_hi[HM];   // sig(qk) hi
__device__ __nv_bfloat16 g_q_lo[HM];
__device__ __nv_bfloat16 g_v_hi[HM];
__device__ __nv_bfloat16 g_v_lo[HM];
__device__ float g_res[HM];

__device__ __forceinline__ float sigmoidf(float v) {
    return 1.0f / (1.0f + expf(-v));
}

// ---------------- mma / async helpers (plain sm_80+ features) ----------------
__device__ __forceinline__ uint32_t smem_u32(const void* p) {
    return (uint32_t)__cvta_generic_to_shared((void*)p);
}
__device__ __forceinline__ void cp16(uint32_t dst, const void* src) {
    asm volatile("cp.async.cg.shared.global [%0], [%1], 16;" :: "r"(dst), "l"(src));
}
__device__ __forceinline__ void cp_commit() {
    asm volatile("cp.async.commit_group;" ::: "memory");
}
template<int N> __device__ __forceinline__ void cp_wait() {
    asm volatile("cp.async.wait_group %0;" :: "n"(N) : "memory");
}
__device__ __forceinline__ void ldm4(uint32_t* r, uint32_t addr) {
    asm volatile("ldmatrix.sync.aligned.m8n8.x4.shared.b16 {%0,%1,%2,%3},[%4];"
        : "=r"(r[0]), "=r"(r[1]), "=r"(r[2]), "=r"(r[3]) : "r"(addr));
}
__device__ __forceinline__ void ldm4t(uint32_t* r, uint32_t addr) {
    asm volatile("ldmatrix.sync.aligned.m8n8.x4.trans.shared.b16 {%0,%1,%2,%3},[%4];"
        : "=r"(r[0]), "=r"(r[1]), "=r"(r[2]), "=r"(r[3]) : "r"(addr));
}
__device__ __forceinline__ void mma16816(float* d, const uint32_t* a, const uint32_t* b) {
    asm volatile("mma.sync.aligned.m16n8k16.row.col.f32.bf16.bf16.f32 "
        "{%0,%1,%2,%3},{%4,%5,%6,%7},{%8,%9},{%0,%1,%2,%3};"
        : "+f"(d[0]), "+f"(d[1]), "+f"(d[2]), "+f"(d[3])
        : "r"(a[0]), "r"(a[1]), "r"(a[2]), "r"(a[3]), "r"(b[0]), "r"(b[1]));
}
// tf32 m16n8k8 (operands pre-rounded to tf32 at prep)
__device__ __forceinline__ void mma1688t(float* d, const uint32_t* a, const uint32_t* b) {
    asm volatile("mma.sync.aligned.m16n8k8.row.col.f32.tf32.tf32.f32 "
        "{%0,%1,%2,%3},{%4,%5,%6,%7},{%8,%9},{%0,%1,%2,%3};"
        : "+f"(d[0]), "+f"(d[1]), "+f"(d[2]), "+f"(d[3])
        : "r"(a[0]), "r"(a[1]), "r"(a[2]), "r"(a[3]), "r"(b[0]), "r"(b[1]));
}
__device__ __forceinline__ float tf32r(float v) {
    uint32_t r;
    asm("cvt.rna.tf32.f32 %0, %1;" : "=r"(r) : "f"(v));
    return __uint_as_float(r);
}
__device__ __forceinline__ uint32_t bpack(__nv_bfloat16 a, __nv_bfloat16 b) {
    __nv_bfloat162 t = __halves2bfloat162(a, b);
    return *(uint32_t*)&t;
}
__device__ __forceinline__ void bsplit(float v, __nv_bfloat16& h, __nv_bfloat16& l) {
    h = __float2bfloat16(v);
    l = __float2bfloat16(v - __bfloat162float(h));
}

// ---------------------------------------------------------------------------
// K1: fused prep. Blocks [0,1024): degree+gate -> tf32-rounded fp32.
//     Blocks [1024,4096): W transpose -> tf32-rounded fp32.
// ---------------------------------------------------------------------------
#define DGATE_BLOCKS (MM/8)              // 1024
#define WPREP_BLOCKS ((N3/32)*(CC/32))   // 3072

__global__ __launch_bounds__(256) void prep_kernel(const float* __restrict__ adj,
                                                   const float* __restrict__ x,
                                                   const float* __restrict__ Wd,
                                                   const float* __restrict__ bd,
                                                   const float* __restrict__ W) {
    __shared__ float t[32][33];
    int tid = threadIdx.x;

    if (blockIdx.x < DGATE_BLOCKS) {
        int row = (blockIdx.x * 256 + tid) >> 5;
        int lane = tid & 31;
        const float4* arow = (const float4*)(adj + (size_t)row * LL);
        float s = 0.0f;
        #pragma unroll
        for (int j = 0; j < 4; j++) {
            float4 v = arow[lane + 32*j];
            s += v.x + v.y + v.z + v.w;
        }
        #pragma unroll
        for (int o = 16; o > 0; o >>= 1) s += __shfl_xor_sync(0xffffffffu, s, o);
        float deg = s;

        const float4* xr = (const float4*)(x + (size_t)row * CC);
        #pragma unroll
        for (int j = 0; j < 8; j++) {
            int c4 = lane + 32*j;
            float4 xv = xr[c4];
            float4 wv = ((const float4*)Wd)[c4];
            float4 bv = ((const float4*)bd)[c4];
            float4 o;
            o.x = tf32r(xv.x * sigmoidf(deg*wv.x + bv.x));
            o.y = tf32r(xv.y * sigmoidf(deg*wv.y + bv.y));
            o.z = tf32r(xv.z * sigmoidf(deg*wv.z + bv.z));
            o.w = tf32r(xv.w * sigmoidf(deg*wv.w + bv.w));
            ((float4*)(g_a32 + (size_t)row * CC))[c4] = o;
        }
    } else {
        int bid = blockIdx.x - DGATE_BLOCKS;
        int n0 = (bid % (N3/32)) * 32;
        int k0 = (bid / (N3/32)) * 32;
        int tx = tid & 31, ty = tid >> 5;     // (32, 8)
        #pragma unroll
        for (int i = ty; i < 32; i += 8)
            t[i][tx] = W[(size_t)(k0 + i) * N3 + n0 + tx];
        __syncthreads();
        #pragma unroll
        for (int i = ty; i < 32; i += 8)
            g_w32[(size_t)(n0 + i) * CC + k0 + tx] = tf32r(t[tx][i]);
    }
}

// ---------------------------------------------------------------------------
// K3: TF32 single-term GEMM, 128x128 tile, k32 chunks, 2-stage cp.async,
// 2 CTA/SM. Per warp per chunk: 24 ldmatrix + 64 mma.m16n8k8.tf32.
// Rows 144B: 8-row offsets mod 128 = {0,16,...,112} -> conflict-free, aligned.
// ---------------------------------------------------------------------------
#define ROWB 144                     // bytes per smem row (32 fp32 + 16B pad)
#define TILE (128*ROWB)              // 18432 B
#define STAGE (2*TILE)               // A|B = 36864 B
#define SG_SMEM (2*STAGE)            // 73728 B -> 2 CTA/SM

__global__ __launch_bounds__(256) void sgemm_mma(const float* __restrict__ bias) {
    extern __shared__ char sm[];
    uint32_t smb = smem_u32(sm);
    int tid = threadIdx.x, wid = tid >> 5, lane = tid & 31;
    int bx = blockIdx.x, by = blockIdx.y;
    int wm = wid & 3;        // 4 warps over M (32 rows)
    int wn = wid >> 2;       // 2 warps over N (64 cols)

    const float* A = g_a32 + (size_t)by * 128 * CC;
    const float* B = g_w32 + (size_t)bx * 128 * CC;

    float acc[2][8][4];
    #pragma unroll
    for (int t = 0; t < 2; t++)
        #pragma unroll
        for (int j = 0; j < 8; j++)
            #pragma unroll
            for (int u = 0; u < 4; u++) acc[t][j][u] = 0.0f;

    auto load_chunk = [&](int stage, int k0) {
        uint32_t base = smb + stage * STAGE;
        #pragma unroll
        for (int q = 0; q < 4; q++) {
            int c = tid + 256 * q;
            int row = c >> 3, s = c & 7;        // 128 rows x 8 segs(16B)
            uint32_t off = (uint32_t)(row * ROWB + s * 16);
            size_t go = (size_t)row * CC + k0 + s * 4;
            cp16(base + off,        A + go);
            cp16(base + TILE + off, B + go);
        }
        cp_commit();
    };

    int li = lane >> 3, lr = lane & 7;
    // A x4: m0=(r+0,k-lo) m1=(r+8,k-lo) m2=(r+0,k-hi) m3=(r+8,k-hi)
    int a_row = wm * 32 + (li & 1) * 8 + lr;
    uint32_t a_kb = (uint32_t)((li >> 1) * 16);
    // B x4: m0=(n+0,k-lo) m1=(n+0,k-hi) m2=(n+8,k-lo) m3=(n+8,k-hi)
    int b_rowbase = wn * 64 + (li >> 1) * 8 + lr;
    uint32_t b_kb = (uint32_t)((li & 1) * 16);

    load_chunk(0, 0);

    #pragma unroll 1
    for (int i = 0; i < 32; i++) {
        cp_wait<0>();
        __syncthreads();
        if (i < 31) load_chunk((i + 1) & 1, (i + 1) * 32);

        uint32_t sb = smb + (i & 1) * STAGE;
        #pragma unroll
        for (int ks = 0; ks < 4; ks++) {        // k8 steps within k32
            uint32_t af[2][4];
            #pragma unroll
            for (int t = 0; t < 2; t++) {
                uint32_t aoff = (uint32_t)((a_row + t*16) * ROWB) + ks*32 + a_kb;
                ldm4(af[t], sb + aoff);
            }
            uint32_t bf[4][4];
            #pragma unroll
            for (int bb = 0; bb < 4; bb++) {    // covers n-blocks 2bb,2bb+1
                uint32_t boff = (uint32_t)((b_rowbase + bb*16) * ROWB) + ks*32 + b_kb;
                ldm4(bf[bb], sb + TILE + boff);
            }
            #pragma unroll
            for (int t = 0; t < 2; t++) {
                #pragma unroll
                for (int j = 0; j < 8; j++) {
                    const uint32_t* bp = &bf[j >> 1][(j & 1) * 2];
                    mma1688t(acc[t][j], af[t], bp);
                }
            }
        }
    }

    // epilogue -> head-major arrays
    int third = bx >> 3;          // 0=qk, 1=res, 2=value
    int head = bx & 7;
    #pragma unroll
    for (int t = 0; t < 2; t++) {
        int gr0 = by * 128 + wm * 32 + t * 16 + (lane >> 2);
        #pragma unroll
        for (int j = 0; j < 8; j++) {
            int col = wn * 64 + j * 8 + (lane & 3) * 2;
            float bx0 = bias[bx * 128 + col];
            float bx1 = bias[bx * 128 + col + 1];
            #pragma unroll
            for (int rsel = 0; rsel < 2; rsel++) {
                int gr = gr0 + rsel * 8;
                float v0 = acc[t][j][rsel*2 + 0] + bx0;
                float v1 = acc[t][j][rsel*2 + 1] + bx1;
                int b = gr >> 9, l = gr & 511;
                size_t idx = ((size_t)((b << 3) + head) * LL + l) * HD + col;
                if (third == 0) {
                    v0 = sigmoidf(v0); v1 = sigmoidf(v1);
                    __nv_bfloat16 h0,l0,h1,l1;
                    bsplit(v0,h0,l0); bsplit(v1,h1,l1);
                    *(uint32_t*)&g_q_hi[idx] = bpack(h0,h1);
                    *(uint32_t*)&g_q_lo[idx] = bpack(l0,l1);
                } else if (third == 1) {
                    *(float2*)&g_res[idx] = make_float2(v0, v1);
                } else {
                    __nv_bfloat16 h0,l0,h1,l1;
                    bsplit(v0,h0,l0); bsplit(v1,h1,l1);
                    *(uint32_t*)&g_v_hi[idx] = bpack(h0,h1);
                    *(uint32_t*)&g_v_lo[idx] = bpack(l0,l1);
                }
            }
        }
    }
}

// ---------------------------------------------------------------------------
// K4: HMMA attention, Q fragments hoisted to registers (round-10/14 best).
// ---------------------------------------------------------------------------
#define QROWB 272
#define KROWB 272
#define ADJROWB 144
#define QTILE (128*QROWB)
#define KTILE (32*KROWB)
#define STAGEA (4*KTILE + 128*ADJROWB)
#define AT_SMEM (2*QTILE + 2*STAGEA)

__global__ __launch_bounds__(256, 1) void attn3_kernel(const float* __restrict__ adj,
                                                       float* __restrict__ out) {
    extern __shared__ char sm[];
    uint32_t smb = smem_u32(sm);
    int tid = threadIdx.x, warp = tid >> 5, lane = tid & 31;
    int li = lane >> 3, lr = lane & 7;
    int rt = blockIdx.x, bh = blockIdx.y;
    int b = bh >> 3, h = bh & 7;
    int r0 = rt * 128;
    int wr = warp * 16;

    const uint32_t QH = smb, QL = smb + QTILE;
    const float scale = 0.08838834764831845f;

    #pragma unroll
    for (int i = 0; i < 16; i++) {
        int idx = tid + 256 * i;
        int arr = idx >> 11, rem = idx & 2047;
        int row = rem >> 4, seg = rem & 15;
        const __nv_bfloat16* src = arr ? g_q_lo : g_q_hi;
        cp16(QH + arr*QTILE + (uint32_t)(row*QROWB + seg*16),
             src + ((size_t)bh*LL + r0 + row)*HD + seg*8);
    }
    cp_commit();

    auto load_stage = [&](int s, int c0) {
        uint32_t SB = smb + 2*QTILE + s*STAGEA;
        #pragma unroll
        for (int i = 0; i < 12; i++) {
            int idx = tid + 256 * i;
            if (idx < 2048) {
                int which = idx >> 10;
                int arr = (idx >> 9) & 1;
                int rem = idx & 511;
                int row = rem >> 4, seg = rem & 15;
                const __nv_bfloat16* src =
                    which ? (arr ? g_v_lo : g_v_hi) : (arr ? g_q_lo : g_q_hi);
                cp16(SB + which*2*KTILE + arr*KTILE + (uint32_t)(row*KROWB + seg*16),
                     src + ((size_t)bh*LL + c0 + row)*HD + seg*8);
            } else {
                int rem = idx - 2048;
                int row = rem >> 3, g = rem & 7;
                cp16(SB + 4*KTILE + (uint32_t)(row*ADJROWB + g*16),
                     adj + ((size_t)(b*LL + r0 + row))*LL + c0 + g*4);
            }
        }
        cp_commit();
    };

    load_stage(0, 0);
    cp_wait<0>();
    __syncthreads();

    // hoist Q fragments: invariant across all key chunks
    uint32_t qh[8][4], ql[8][4];
    #pragma unroll
    for (int ks = 0; ks < 8; ks++) {
        uint32_t aoff = (uint32_t)((wr + (li&1)*8 + lr)*QROWB + ks*32 + (li>>1)*16);
        ldm4(qh[ks], QH + aoff);
        ldm4(ql[ks], QL + aoff);
    }

    float Oacc[16][4];
    #pragma unroll
    for (int n = 0; n < 16; n++)
        #pragma unroll
        for (int u = 0; u < 4; u++) Oacc[n][u] = 0.0f;
    float d0 = 0.0f, d1 = 0.0f;

    #pragma unroll 1
    for (int c = 0; c < 16; c++) {
        if (c < 15) load_stage((c + 1) & 1, (c + 1) * 32);

        uint32_t SB = smb + 2*QTILE + (c & 1)*STAGEA;
        uint32_t KHB = SB, KLB = SB + KTILE, VHB = SB + 2*KTILE, VLB = SB + 3*KTILE;
        const float* adjs = (const float*)(sm + 2*QTILE + (c & 1)*STAGEA + 4*KTILE);

        float S[4][4];
        #pragma unroll
        for (int j = 0; j < 4; j++)
            #pragma unroll
            for (int u = 0; u < 4; u++) S[j][u] = 0.0f;

        #pragma unroll
        for (int ks = 0; ks < 8; ks++) {
            uint32_t kh[2][4], kl[2][4];
            #pragma unroll
            for (int g = 0; g < 2; g++) {
                uint32_t boff = (uint32_t)((g*16 + (li>>1)*8 + lr)*KROWB + ks*32 + (li&1)*16);
                ldm4(kh[g], KHB + boff);
                ldm4(kl[g], KLB + boff);
            }
            #pragma unroll
            for (int j = 0; j < 4; j++) {
                const uint32_t* ph = &kh[j>>1][(j&1)*2];
                const uint32_t* pl = &kl[j>>1][(j&1)*2];
                mma16816(S[j], qh[ks], ph);
                mma16816(S[j], qh[ks], pl);
                mma16816(S[j], ql[ks], ph);
            }
        }

        uint32_t Th[4][2], Tl[4][2];
        int ra = wr + (lane >> 2);
        #pragma unroll
        for (int j = 0; j < 4; j++) {
            int cb = j*8 + (lane & 3)*2;
            float a00 = adjs[ra*36 + cb],     a01 = adjs[ra*36 + cb + 1];
            float a10 = adjs[(ra+8)*36 + cb], a11 = adjs[(ra+8)*36 + cb + 1];
            float T00 = (a00 != 0.0f) ? S[j][0]*scale : 0.0f;
            float T01 = (a01 != 0.0f) ? S[j][1]*scale : 0.0f;
            float T10 = (a10 != 0.0f) ? S[j][2]*scale : 0.0f;
            float T11 = (a11 != 0.0f) ? S[j][3]*scale : 0.0f;
            d0 += T00 + T01;
            d1 += T10 + T11;
            __nv_bfloat16 h0,l0,h1,l1;
            bsplit(T00,h0,l0); bsplit(T01,h1,l1);
            Th[j][0] = bpack(h0,h1); Tl[j][0] = bpack(l0,l1);
            bsplit(T10,h0,l0); bsplit(T11,h1,l1);
            Th[j][1] = bpack(h0,h1); Tl[j][1] = bpack(l0,l1);
        }

        #pragma unroll
        for (int kk = 0; kk < 2; kk++) {
            uint32_t ahf[4] = {Th[2*kk][0], Th[2*kk][1], Th[2*kk+1][0], Th[2*kk+1][1]};
            uint32_t alf[4] = {Tl[2*kk][0], Tl[2*kk][1], Tl[2*kk+1][0], Tl[2*kk+1][1]};
            #pragma unroll
            for (int g = 0; g < 8; g++) {
                uint32_t bh4[4], bl4[4];
                uint32_t voff = (uint32_t)((kk*16 + (li&1)*8 + lr)*KROWB + g*32 + (li>>1)*16);
                ldm4t(bh4, VHB + voff);
                ldm4t(bl4, VLB + voff);
                #pragma unroll
                for (int j = 0; j < 2; j++) {
                    int nt = g*2 + j;
                    const uint32_t* pb = &bh4[j*2];
                    const uint32_t* pl = &bl4[j*2];
                    mma16816(Oacc[nt], ahf, pb);
                    mma16816(Oacc[nt], ahf, pl);
                    mma16816(Oacc[nt], alf, pb);
                }
            }
        }

        if (c < 15) {
            cp_wait<0>();
            __syncthreads();
        }
    }

    d0 += __shfl_xor_sync(0xffffffffu, d0, 1);
    d0 += __shfl_xor_sync(0xffffffffu, d0, 2);
    d1 += __shfl_xor_sync(0xffffffffu, d1, 1);
    d1 += __shfl_xor_sync(0xffffffffu, d1, 2);
    float inv0 = 1.0f / (d0 + 1e-6f);
    float inv1 = 1.0f / (d1 + 1e-6f);

    int gr0 = r0 + wr + (lane >> 2);
    #pragma unroll
    for (int nt = 0; nt < 16; nt++) {
        int col = nt*8 + (lane & 3)*2;
        size_t i0 = ((size_t)bh*LL + gr0)*HD + col;
        float2 rs0 = *(const float2*)(g_res + i0);
        float2 rs1 = *(const float2*)(g_res + i0 + 8*HD);
        float* o0 = out + ((size_t)(b*LL + gr0))*CC + h*HD + col;
        *(float2*)o0 = make_float2(
            fmaxf(Oacc[nt][0]*inv0 + rs0.x, 0.0f),
            fmaxf(Oacc[nt][1]*inv0 + rs0.y, 0.0f));
        *(float2*)(o0 + 8*CC) = make_float2(
            fmaxf(Oacc[nt][2]*inv1 + rs1.x, 0.0f),
            fmaxf(Oacc[nt][3]*inv1 + rs1.y, 0.0f));
    }
}

// ---------------------------------------------------------------------------
extern "C" void kernel_launch(void* const* d_in, const int* in_sizes, int n_in,
                              void* d_out, int out_size) {
    const float* x    = (const float*)d_in[0];
    const float* adj  = (const float*)d_in[1];
    const float* Wqkv = (const float*)d_in[2];
    const float* bqkv = (const float*)d_in[3];
    const float* Wd   = (const float*)d_in[4];
    const float* bd   = (const float*)d_in[5];
    float* out = (float*)d_out;

    cudaFuncSetAttribute(sgemm_mma,
                         cudaFuncAttributeMaxDynamicSharedMemorySize, SG_SMEM);
    cudaFuncSetAttribute(attn3_kernel,
                         cudaFuncAttributeMaxDynamicSharedMemorySize, AT_SMEM);

    prep_kernel<<<DGATE_BLOCKS + WPREP_BLOCKS, 256>>>(adj, x, Wd, bd, Wqkv);
    sgemm_mma<<<dim3(N3/128, MM/128), 256, SG_SMEM>>>(bqkv);
    attn3_kernel<<<dim3(LL/128, NH*BB), 256, AT_SMEM>>>(adj, out);
}